// round 1
// baseline (speedup 1.0000x reference)
#include <cuda_runtime.h>

#define CB   4
#define CN   2048
#define CH   8
#define CDH  64
#define CDIM 512
#define ATT_SCALE 0.125f   // 64^-0.5

// scratch (allocation-free rule: __device__ globals)
__device__ float g_q[CB * CN * CDIM];
__device__ float g_k[CB * CN * CDIM];
__device__ float g_v[CB * CN * CDIM];
__device__ float g_o[CB * CN * CDIM];

// ---------------------------------------------------------------------------
// C[m][n] = sum_k A[m][k] * W[n][k]     (A: [M,K] row-major, W: [Nc,K] row-major)
// 128x128 block tile, BK=16, 256 threads, 8x8 per-thread micro-tile.
// ---------------------------------------------------------------------------
__global__ __launch_bounds__(256) void gemm_nt_kernel(
    const float* __restrict__ A, const float* __restrict__ W,
    float* __restrict__ C, int M, int Nc, int K)
{
    __shared__ float As[16][132];   // As[k][m], pad keeps float4 alignment
    __shared__ float Ws[16][132];   // Ws[k][n]

    const int tid = threadIdx.x;
    const int ty  = tid >> 4;
    const int tx  = tid & 15;
    const int rowBase = blockIdx.y * 128;
    const int colBase = blockIdx.x * 128;

    float acc[8][8];
#pragma unroll
    for (int i = 0; i < 8; i++)
#pragma unroll
        for (int j = 0; j < 8; j++) acc[i][j] = 0.f;

    for (int kt = 0; kt < K; kt += 16) {
#pragma unroll
        for (int i = 0; i < 2; i++) {
            int idx = tid + i * 256;           // 0..511 float4 units
            int r   = idx >> 2;                // 0..127 (tile row)
            int c4  = (idx & 3) << 2;          // 0,4,8,12 (k offset)
            float4 va = *(const float4*)(A + (size_t)(rowBase + r) * K + kt + c4);
            As[c4 + 0][r] = va.x; As[c4 + 1][r] = va.y;
            As[c4 + 2][r] = va.z; As[c4 + 3][r] = va.w;
            float4 vw = *(const float4*)(W + (size_t)(colBase + r) * K + kt + c4);
            Ws[c4 + 0][r] = vw.x; Ws[c4 + 1][r] = vw.y;
            Ws[c4 + 2][r] = vw.z; Ws[c4 + 3][r] = vw.w;
        }
        __syncthreads();

#pragma unroll
        for (int kk = 0; kk < 16; kk++) {
            float a[8], b[8];
            float4 t0 = *(const float4*)&As[kk][8 * ty];
            float4 t1 = *(const float4*)&As[kk][8 * ty + 4];
            a[0]=t0.x; a[1]=t0.y; a[2]=t0.z; a[3]=t0.w;
            a[4]=t1.x; a[5]=t1.y; a[6]=t1.z; a[7]=t1.w;
            float4 u0 = *(const float4*)&Ws[kk][8 * tx];
            float4 u1 = *(const float4*)&Ws[kk][8 * tx + 4];
            b[0]=u0.x; b[1]=u0.y; b[2]=u0.z; b[3]=u0.w;
            b[4]=u1.x; b[5]=u1.y; b[6]=u1.z; b[7]=u1.w;
#pragma unroll
            for (int i = 0; i < 8; i++)
#pragma unroll
                for (int j = 0; j < 8; j++)
                    acc[i][j] += a[i] * b[j];
        }
        __syncthreads();
    }

#pragma unroll
    for (int i = 0; i < 8; i++) {
        float* cp = C + (size_t)(rowBase + 8 * ty + i) * Nc + colBase + 8 * tx;
        *(float4*)(cp)     = make_float4(acc[i][0], acc[i][1], acc[i][2], acc[i][3]);
        *(float4*)(cp + 4) = make_float4(acc[i][4], acc[i][5], acc[i][6], acc[i][7]);
    }
}

// ---------------------------------------------------------------------------
// Flash attention per (h,b) pair, 64-query tile per block, 64-key tiles.
// Masked-fill is a CONSTANT 1e-9 (per reference), then standard softmax.
// Q pre-scaled by ATT_SCALE. smem staged transposed so all inner loops are LDS.128.
// ---------------------------------------------------------------------------
__global__ __launch_bounds__(256) void attn_kernel(
    const float* __restrict__ Q, const float* __restrict__ K,
    const float* __restrict__ V, const int* __restrict__ mask,
    float* __restrict__ O)
{
    extern __shared__ float smem[];
    float* Qs = smem;                 // [64][68]  Qs[dh][q]
    float* Ks = smem + 64 * 68;       // [64][68]  Ks[dh][key]
    float* Vs = smem + 2 * 64 * 68;   // [64][68]  Vs[key][dh]
    float* Ps = smem + 3 * 64 * 68;   // [64][68]  Ps[key][q]
    int*   Ms = (int*)(smem + 4 * 64 * 68);

    const int tid = threadIdx.x;
    const int ty  = tid >> 4;         // 0..15 -> query rows 4*ty..4*ty+3
    const int tx  = tid & 15;         // 0..15 -> key cols / dh cols 4*tx..4*tx+3
    const int q0  = blockIdx.x * 64;
    const int h   = blockIdx.y & 7;
    const int b   = blockIdx.y >> 3;
    const int cb  = h * CDH;          // channel base (head-major layout)

    // load Q tile, transposed + pre-scaled
#pragma unroll
    for (int i = 0; i < 4; i++) {
        int idx = tid + i * 256;      // float4 index 0..1023
        int r   = idx >> 4;           // row 0..63
        int c4  = (idx & 15) << 2;    // dh 0..60
        float4 vq = *(const float4*)(Q + (size_t)(b * CN + q0 + r) * CDIM + cb + c4);
        Qs[(c4 + 0) * 68 + r] = vq.x * ATT_SCALE;
        Qs[(c4 + 1) * 68 + r] = vq.y * ATT_SCALE;
        Qs[(c4 + 2) * 68 + r] = vq.z * ATT_SCALE;
        Qs[(c4 + 3) * 68 + r] = vq.w * ATT_SCALE;
    }

    float m_i[4], l_i[4], acc[4][4];
#pragma unroll
    for (int i = 0; i < 4; i++) {
        m_i[i] = -1e30f; l_i[i] = 0.f;
#pragma unroll
        for (int j = 0; j < 4; j++) acc[i][j] = 0.f;
    }

    for (int kb = 0; kb < CN; kb += 64) {
        __syncthreads();   // prev iteration's PV gemm done (Vs/Ps/Ks reusable)

#pragma unroll
        for (int i = 0; i < 4; i++) {
            int idx = tid + i * 256;
            int r   = idx >> 4;
            int c4  = (idx & 15) << 2;
            float4 vk = *(const float4*)(K + (size_t)(b * CN + kb + r) * CDIM + cb + c4);
            Ks[(c4 + 0) * 68 + r] = vk.x;
            Ks[(c4 + 1) * 68 + r] = vk.y;
            Ks[(c4 + 2) * 68 + r] = vk.z;
            Ks[(c4 + 3) * 68 + r] = vk.w;
            float4 vv = *(const float4*)(V + (size_t)(b * CN + kb + r) * CDIM + cb + c4);
            *(float4*)&Vs[r * 68 + c4] = vv;
        }
        if (tid < 64) Ms[tid] = mask[b * CN + kb + tid];
        __syncthreads();

        // S = (Q*scale) K^T : 4x4 per thread
        float s[4][4];
#pragma unroll
        for (int i = 0; i < 4; i++)
#pragma unroll
            for (int j = 0; j < 4; j++) s[i][j] = 0.f;

#pragma unroll 16
        for (int d = 0; d < 64; d++) {
            float4 aq = *(const float4*)&Qs[d * 68 + 4 * ty];
            float4 bk = *(const float4*)&Ks[d * 68 + 4 * tx];
            s[0][0] += aq.x * bk.x; s[0][1] += aq.x * bk.y; s[0][2] += aq.x * bk.z; s[0][3] += aq.x * bk.w;
            s[1][0] += aq.y * bk.x; s[1][1] += aq.y * bk.y; s[1][2] += aq.y * bk.z; s[1][3] += aq.y * bk.w;
            s[2][0] += aq.z * bk.x; s[2][1] += aq.z * bk.y; s[2][2] += aq.z * bk.z; s[2][3] += aq.z * bk.w;
            s[3][0] += aq.w * bk.x; s[3][1] += aq.w * bk.y; s[3][2] += aq.w * bk.z; s[3][3] += aq.w * bk.w;
        }

        // constant masked-fill (reference semantics: 1e-9, NOT -inf)
#pragma unroll
        for (int j = 0; j < 4; j++) {
            if (Ms[4 * tx + j] == 0) {
                s[0][j] = 1e-9f; s[1][j] = 1e-9f; s[2][j] = 1e-9f; s[3][j] = 1e-9f;
            }
        }

        // online softmax per query row (row group = 16 tx lanes, same warp half)
        float p[4][4];
#pragma unroll
        for (int i = 0; i < 4; i++) {
            float rm = fmaxf(fmaxf(s[i][0], s[i][1]), fmaxf(s[i][2], s[i][3]));
            rm = fmaxf(rm, __shfl_xor_sync(0xffffffffu, rm, 1));
            rm = fmaxf(rm, __shfl_xor_sync(0xffffffffu, rm, 2));
            rm = fmaxf(rm, __shfl_xor_sync(0xffffffffu, rm, 4));
            rm = fmaxf(rm, __shfl_xor_sync(0xffffffffu, rm, 8));
            float mn    = fmaxf(m_i[i], rm);
            float alpha = __expf(m_i[i] - mn);
            float rs = 0.f;
#pragma unroll
            for (int j = 0; j < 4; j++) {
                p[i][j] = __expf(s[i][j] - mn);
                rs += p[i][j];
            }
            rs += __shfl_xor_sync(0xffffffffu, rs, 1);
            rs += __shfl_xor_sync(0xffffffffu, rs, 2);
            rs += __shfl_xor_sync(0xffffffffu, rs, 4);
            rs += __shfl_xor_sync(0xffffffffu, rs, 8);
            l_i[i] = l_i[i] * alpha + rs;
            m_i[i] = mn;
#pragma unroll
            for (int j = 0; j < 4; j++) acc[i][j] *= alpha;
        }

        // store P transposed: Ps[key][q], float4 per column
#pragma unroll
        for (int j = 0; j < 4; j++) {
            *(float4*)&Ps[(4 * tx + j) * 68 + 4 * ty] =
                make_float4(p[0][j], p[1][j], p[2][j], p[3][j]);
        }
        __syncthreads();

        // O += P V
#pragma unroll 16
        for (int ss = 0; ss < 64; ss++) {
            float4 pv = *(const float4*)&Ps[ss * 68 + 4 * ty];
            float4 vv = *(const float4*)&Vs[ss * 68 + 4 * tx];
            acc[0][0] += pv.x * vv.x; acc[0][1] += pv.x * vv.y; acc[0][2] += pv.x * vv.z; acc[0][3] += pv.x * vv.w;
            acc[1][0] += pv.y * vv.x; acc[1][1] += pv.y * vv.y; acc[1][2] += pv.y * vv.z; acc[1][3] += pv.y * vv.w;
            acc[2][0] += pv.z * vv.x; acc[2][1] += pv.z * vv.y; acc[2][2] += pv.z * vv.z; acc[2][3] += pv.z * vv.w;
            acc[3][0] += pv.w * vv.x; acc[3][1] += pv.w * vv.y; acc[3][2] += pv.w * vv.z; acc[3][3] += pv.w * vv.w;
        }
    }

    // epilogue: divide by row sum, write head-major channels
#pragma unroll
    for (int i = 0; i < 4; i++) {
        float inv = 1.f / l_i[i];
        float4 r4 = make_float4(acc[i][0] * inv, acc[i][1] * inv,
                                acc[i][2] * inv, acc[i][3] * inv);
        *(float4*)(O + (size_t)(b * CN + q0 + 4 * ty + i) * CDIM + cb + 4 * tx) = r4;
    }
}

// ---------------------------------------------------------------------------
extern "C" void kernel_launch(void* const* d_in, const int* in_sizes, int n_in,
                              void* d_out, int out_size)
{
    const float* x    = (const float*)d_in[0];
    const int*   mask = (const int*)  d_in[1];
    const float* Wq   = (const float*)d_in[2];
    const float* Wk   = (const float*)d_in[3];
    const float* Wv   = (const float*)d_in[4];
    const float* Wout = (const float*)d_in[5];
    float* out = (float*)d_out;

    float *qp, *kp, *vp, *op;
    cudaGetSymbolAddress((void**)&qp, g_q);
    cudaGetSymbolAddress((void**)&kp, g_k);
    cudaGetSymbolAddress((void**)&vp, g_v);
    cudaGetSymbolAddress((void**)&op, g_o);

    const int M = CB * CN;                 // 8192
    dim3 ggrid(CDIM / 128, M / 128);       // (4, 64)

    gemm_nt_kernel<<<ggrid, 256>>>(x, Wq, qp, M, CDIM, CDIM);
    gemm_nt_kernel<<<ggrid, 256>>>(x, Wk, kp, M, CDIM, CDIM);
    gemm_nt_kernel<<<ggrid, 256>>>(x, Wv, vp, M, CDIM, CDIM);

    const int smem_bytes = 4 * 64 * 68 * (int)sizeof(float) + 64 * (int)sizeof(int); // 69888
    cudaFuncSetAttribute(attn_kernel, cudaFuncAttributeMaxDynamicSharedMemorySize, smem_bytes);
    attn_kernel<<<dim3(CN / 64, CH * CB), 256, smem_bytes>>>(qp, kp, vp, mask, op);

    gemm_nt_kernel<<<ggrid, 256>>>(op, Wout, out, M, CDIM, CDIM);
}

// round 3
// speedup vs baseline: 2.4947x; 2.4947x over previous
#include <cuda_runtime.h>
#include <cuda_bf16.h>
#include <cstdint>

#define CB   4
#define CN   2048
#define CH   8
#define CDH  64
#define CDIM 512
#define ATT_SCALE 0.125f
#define SSTR 72            // smem row stride in bf16 (64 data + 8 pad) -> conflict-free frags

// ---------------- scratch (__device__ globals; no allocation allowed) -------
__device__ float g_q[CB * CN * CDIM];
__device__ float g_k[CB * CN * CDIM];
__device__ float g_v[CB * CN * CDIM];
__device__ float g_o[CB * CN * CDIM];
__device__ __nv_bfloat16 g_xhi[CB * CN * CDIM];
__device__ __nv_bfloat16 g_xlo[CB * CN * CDIM];
__device__ __nv_bfloat16 g_ohi[CB * CN * CDIM];
__device__ __nv_bfloat16 g_olo[CB * CN * CDIM];
__device__ __nv_bfloat16 g_wh[4][CDIM * CDIM];
__device__ __nv_bfloat16 g_wl[4][CDIM * CDIM];

// ---------------- helpers ----------------------------------------------------
__device__ __forceinline__ void mma16816(float* c, const uint32_t* a, uint32_t b0, uint32_t b1) {
    asm volatile(
        "mma.sync.aligned.m16n8k16.row.col.f32.bf16.bf16.f32 "
        "{%0,%1,%2,%3}, {%4,%5,%6,%7}, {%8,%9}, {%0,%1,%2,%3};\n"
        : "+f"(c[0]), "+f"(c[1]), "+f"(c[2]), "+f"(c[3])
        : "r"(a[0]), "r"(a[1]), "r"(a[2]), "r"(a[3]), "r"(b0), "r"(b1));
}
__device__ __forceinline__ uint32_t packbf(__nv_bfloat16 x, __nv_bfloat16 y) {
    __nv_bfloat162 t = __halves2bfloat162(x, y);   // x -> low half (element k), y -> high (k+1)
    return *reinterpret_cast<uint32_t*>(&t);
}

// ---------------- fp32 -> bf16 hi/lo split -----------------------------------
__global__ void split_kernel(const float* __restrict__ src,
                             __nv_bfloat16* __restrict__ hi,
                             __nv_bfloat16* __restrict__ lo, int n)
{
    int i = (blockIdx.x * blockDim.x + threadIdx.x) * 4;
    if (i >= n) return;
    float4 v = *(const float4*)(src + i);
    __nv_bfloat16 h0 = __float2bfloat16(v.x);
    __nv_bfloat16 h1 = __float2bfloat16(v.y);
    __nv_bfloat16 h2 = __float2bfloat16(v.z);
    __nv_bfloat16 h3 = __float2bfloat16(v.w);
    __nv_bfloat16 l0 = __float2bfloat16(v.x - __bfloat162float(h0));
    __nv_bfloat16 l1 = __float2bfloat16(v.y - __bfloat162float(h1));
    __nv_bfloat16 l2 = __float2bfloat16(v.z - __bfloat162float(h2));
    __nv_bfloat16 l3 = __float2bfloat16(v.w - __bfloat162float(h3));
    ((__nv_bfloat162*)(hi + i))[0] = __halves2bfloat162(h0, h1);
    ((__nv_bfloat162*)(hi + i))[1] = __halves2bfloat162(h2, h3);
    ((__nv_bfloat162*)(lo + i))[0] = __halves2bfloat162(l0, l1);
    ((__nv_bfloat162*)(lo + i))[1] = __halves2bfloat162(l2, l3);
}

// ---------------- bf16-split GEMM via mma.sync -------------------------------
// C[m][n] = sum_k A[m][k] * B[n][k], A/B pre-split bf16 hi/lo, K = 512.
// 128x128 block tile, 256 threads (8 warps as 4M x 2N), warp tile 32x64.
__global__ __launch_bounds__(256, 1) void gemm_mma_kernel(
    const __nv_bfloat16* __restrict__ Ah_g, const __nv_bfloat16* __restrict__ Al_g,
    const __nv_bfloat16* __restrict__ Bh_g, const __nv_bfloat16* __restrict__ Bl_g,
    float* __restrict__ C, int Nc)
{
    extern __shared__ __nv_bfloat16 gs[];
    __nv_bfloat16* Ah = gs;
    __nv_bfloat16* Al = Ah + 128 * SSTR;
    __nv_bfloat16* Bh = Al + 128 * SSTR;
    __nv_bfloat16* Bl = Bh + 128 * SSTR;

    const int tid  = threadIdx.x;
    const int w    = tid >> 5;
    const int lane = tid & 31;
    const int g    = lane >> 2;
    const int tig  = lane & 3;
    const int wM   = w >> 1;           // 0..3 -> rows 32*wM
    const int wN   = w & 1;            // 0..1 -> cols 64*wN
    const int rowBase = blockIdx.y * 128;
    const int colBase = blockIdx.x * 128;

    float acc[2][8][4];
#pragma unroll
    for (int m = 0; m < 2; m++)
#pragma unroll
        for (int j = 0; j < 8; j++)
#pragma unroll
            for (int t = 0; t < 4; t++) acc[m][j][t] = 0.f;

    for (int kc = 0; kc < CDIM; kc += 64) {
        __syncthreads();
#pragma unroll
        for (int i = 0; i < 4; i++) {
            int idx = tid + 256 * i;        // 0..1023 uint4 units (8 bf16 each)
            int r = idx >> 3, u = idx & 7;
            *(uint4*)&Ah[r * SSTR + 8 * u] = *((const uint4*)(Ah_g + (size_t)(rowBase + r) * CDIM + kc) + u);
            *(uint4*)&Al[r * SSTR + 8 * u] = *((const uint4*)(Al_g + (size_t)(rowBase + r) * CDIM + kc) + u);
            *(uint4*)&Bh[r * SSTR + 8 * u] = *((const uint4*)(Bh_g + (size_t)(colBase + r) * CDIM + kc) + u);
            *(uint4*)&Bl[r * SSTR + 8 * u] = *((const uint4*)(Bl_g + (size_t)(colBase + r) * CDIM + kc) + u);
        }
        __syncthreads();

#pragma unroll
        for (int ka = 0; ka < 4; ka++) {
            const int ko = 16 * ka + 2 * tig;
            uint32_t a_h[2][4], a_l[2][4];
#pragma unroll
            for (int m = 0; m < 2; m++) {
                int rb = 32 * wM + 16 * m;
                a_h[m][0] = *(const uint32_t*)&Ah[(rb + g)     * SSTR + ko];
                a_h[m][1] = *(const uint32_t*)&Ah[(rb + g + 8) * SSTR + ko];
                a_h[m][2] = *(const uint32_t*)&Ah[(rb + g)     * SSTR + ko + 8];
                a_h[m][3] = *(const uint32_t*)&Ah[(rb + g + 8) * SSTR + ko + 8];
                a_l[m][0] = *(const uint32_t*)&Al[(rb + g)     * SSTR + ko];
                a_l[m][1] = *(const uint32_t*)&Al[(rb + g + 8) * SSTR + ko];
                a_l[m][2] = *(const uint32_t*)&Al[(rb + g)     * SSTR + ko + 8];
                a_l[m][3] = *(const uint32_t*)&Al[(rb + g + 8) * SSTR + ko + 8];
            }
#pragma unroll
            for (int j = 0; j < 8; j++) {
                int cr = 64 * wN + 8 * j + g;
                uint32_t b0h = *(const uint32_t*)&Bh[cr * SSTR + ko];
                uint32_t b1h = *(const uint32_t*)&Bh[cr * SSTR + ko + 8];
                uint32_t b0l = *(const uint32_t*)&Bl[cr * SSTR + ko];
                uint32_t b1l = *(const uint32_t*)&Bl[cr * SSTR + ko + 8];
#pragma unroll
                for (int m = 0; m < 2; m++) {
                    mma16816(acc[m][j], a_h[m], b0h, b1h);
                    mma16816(acc[m][j], a_h[m], b0l, b1l);
                    mma16816(acc[m][j], a_l[m], b0h, b1h);
                }
            }
        }
    }

#pragma unroll
    for (int m = 0; m < 2; m++)
#pragma unroll
        for (int j = 0; j < 8; j++) {
            int row = rowBase + 32 * wM + 16 * m + g;
            int col = colBase + 64 * wN + 8 * j + 2 * tig;
            *(float2*)&C[(size_t)row * Nc + col]       = make_float2(acc[m][j][0], acc[m][j][1]);
            *(float2*)&C[(size_t)(row + 8) * Nc + col] = make_float2(acc[m][j][2], acc[m][j][3]);
        }
}

// ---------------- flash attention via mma.sync (bf16 split) ------------------
// 128 queries / block, 8 warps x 16 rows. Key tiles of 64. Dh = 64.
__global__ __launch_bounds__(256, 1) void attn_mma_kernel(
    const float* __restrict__ Q, const float* __restrict__ K,
    const float* __restrict__ V, const int* __restrict__ mask,
    float* __restrict__ O)
{
    extern __shared__ __nv_bfloat16 sm[];
    __nv_bfloat16* Qh = sm;
    __nv_bfloat16* Ql = Qh + 128 * SSTR;
    __nv_bfloat16* Kh = Ql + 128 * SSTR;
    __nv_bfloat16* Kl = Kh + 64 * SSTR;
    __nv_bfloat16* Vh = Kl + 64 * SSTR;   // transposed: Vh[dh][key]
    __nv_bfloat16* Vl = Vh + 64 * SSTR;
    int* Ms = (int*)(Vl + 64 * SSTR);

    const int tid  = threadIdx.x;
    const int w    = tid >> 5;
    const int lane = tid & 31;
    const int g    = lane >> 2;
    const int tig  = lane & 3;
    const int q0   = blockIdx.x * 128;
    const int h    = blockIdx.y & 7;
    const int b    = blockIdx.y >> 3;
    const int cb   = h * CDH;

    // ---- load Q tile: scale + split ----
#pragma unroll
    for (int i = 0; i < 8; i++) {
        int idx = tid + 256 * i;          // 0..2047 float4 units
        int r = idx >> 4;
        int c4 = (idx & 15) << 2;
        float4 v = *(const float4*)(Q + (size_t)(b * CN + q0 + r) * CDIM + cb + c4);
        v.x *= ATT_SCALE; v.y *= ATT_SCALE; v.z *= ATT_SCALE; v.w *= ATT_SCALE;
        __nv_bfloat16 h0 = __float2bfloat16(v.x), h1 = __float2bfloat16(v.y);
        __nv_bfloat16 h2 = __float2bfloat16(v.z), h3 = __float2bfloat16(v.w);
        uint2 hv = make_uint2(packbf(h0, h1), packbf(h2, h3));
        uint2 lv = make_uint2(
            packbf(__float2bfloat16(v.x - __bfloat162float(h0)), __float2bfloat16(v.y - __bfloat162float(h1))),
            packbf(__float2bfloat16(v.z - __bfloat162float(h2)), __float2bfloat16(v.w - __bfloat162float(h3))));
        *(uint2*)&Qh[r * SSTR + c4] = hv;
        *(uint2*)&Ql[r * SSTR + c4] = lv;
    }
    __syncthreads();

    // ---- preload Q fragments (warp slab rows 16w..16w+15) ----
    uint32_t qh[4][4], ql[4][4];
#pragma unroll
    for (int ka = 0; ka < 4; ka++) {
        int rb = 16 * w;
        int ko = 16 * ka + 2 * tig;
        qh[ka][0] = *(const uint32_t*)&Qh[(rb + g)     * SSTR + ko];
        qh[ka][1] = *(const uint32_t*)&Qh[(rb + g + 8) * SSTR + ko];
        qh[ka][2] = *(const uint32_t*)&Qh[(rb + g)     * SSTR + ko + 8];
        qh[ka][3] = *(const uint32_t*)&Qh[(rb + g + 8) * SSTR + ko + 8];
        ql[ka][0] = *(const uint32_t*)&Ql[(rb + g)     * SSTR + ko];
        ql[ka][1] = *(const uint32_t*)&Ql[(rb + g + 8) * SSTR + ko];
        ql[ka][2] = *(const uint32_t*)&Ql[(rb + g)     * SSTR + ko + 8];
        ql[ka][3] = *(const uint32_t*)&Ql[(rb + g + 8) * SSTR + ko + 8];
    }

    float o[8][4];
#pragma unroll
    for (int n = 0; n < 8; n++)
#pragma unroll
        for (int t = 0; t < 4; t++) o[n][t] = 0.f;
    float m0 = -1e30f, m1 = -1e30f, l0 = 0.f, l1 = 0.f;

    for (int kb = 0; kb < CN; kb += 64) {
        __syncthreads();   // previous tile's smem fully consumed

        // K tile: split into Kh/Kl [key][dh]
#pragma unroll
        for (int i = 0; i < 4; i++) {
            int idx = tid + 256 * i;      // 0..1023 float4 units
            int r = idx >> 4;
            int c4 = (idx & 15) << 2;
            float4 v = *(const float4*)(K + (size_t)(b * CN + kb + r) * CDIM + cb + c4);
            __nv_bfloat16 h0 = __float2bfloat16(v.x), h1 = __float2bfloat16(v.y);
            __nv_bfloat16 h2 = __float2bfloat16(v.z), h3 = __float2bfloat16(v.w);
            *(uint2*)&Kh[r * SSTR + c4] = make_uint2(packbf(h0, h1), packbf(h2, h3));
            *(uint2*)&Kl[r * SSTR + c4] = make_uint2(
                packbf(__float2bfloat16(v.x - __bfloat162float(h0)), __float2bfloat16(v.y - __bfloat162float(h1))),
                packbf(__float2bfloat16(v.z - __bfloat162float(h2)), __float2bfloat16(v.w - __bfloat162float(h3))));
        }
        // V tile transposed: Vh[dh][key]
        {
            int d = tid & 63;
            int kg0 = tid >> 6;           // 0..3
#pragma unroll
            for (int kgi = 0; kgi < 2; kgi++) {
                int kg = kg0 + 4 * kgi;   // 0..7 (8 keys each)
                float vv[8];
#pragma unroll
                for (int i = 0; i < 8; i++)
                    vv[i] = V[(size_t)(b * CN + kb + kg * 8 + i) * CDIM + cb + d];
#pragma unroll
                for (int p = 0; p < 4; p++) {
                    __nv_bfloat16 ha = __float2bfloat16(vv[2 * p]);
                    __nv_bfloat16 hb = __float2bfloat16(vv[2 * p + 1]);
                    *(uint32_t*)&Vh[d * SSTR + kg * 8 + 2 * p] = packbf(ha, hb);
                    *(uint32_t*)&Vl[d * SSTR + kg * 8 + 2 * p] = packbf(
                        __float2bfloat16(vv[2 * p]     - __bfloat162float(ha)),
                        __float2bfloat16(vv[2 * p + 1] - __bfloat162float(hb)));
                }
            }
        }
        if (tid < 64) Ms[tid] = mask[b * CN + kb + tid];
        __syncthreads();

        // ---- S = Q K^T (3-pass split), fp32 accum ----
        float s[8][4];
#pragma unroll
        for (int j = 0; j < 8; j++)
#pragma unroll
            for (int t = 0; t < 4; t++) s[j][t] = 0.f;
#pragma unroll
        for (int ka = 0; ka < 4; ka++) {
            const int ko = 16 * ka + 2 * tig;
#pragma unroll
            for (int j = 0; j < 8; j++) {
                int kr = 8 * j + g;
                uint32_t b0h = *(const uint32_t*)&Kh[kr * SSTR + ko];
                uint32_t b1h = *(const uint32_t*)&Kh[kr * SSTR + ko + 8];
                uint32_t b0l = *(const uint32_t*)&Kl[kr * SSTR + ko];
                uint32_t b1l = *(const uint32_t*)&Kl[kr * SSTR + ko + 8];
                mma16816(s[j], qh[ka], b0h, b1h);
                mma16816(s[j], qh[ka], b0l, b1l);
                mma16816(s[j], ql[ka], b0h, b1h);
            }
        }

        // ---- mask (constant 1e-9 fill, per reference) ----
#pragma unroll
        for (int j = 0; j < 8; j++) {
            int k0 = 8 * j + 2 * tig;
            if (Ms[k0]     == 0) { s[j][0] = 1e-9f; s[j][2] = 1e-9f; }
            if (Ms[k0 + 1] == 0) { s[j][1] = 1e-9f; s[j][3] = 1e-9f; }
        }

        // ---- online softmax (rows g, g+8 of warp slab; 4-lane shfl groups) ----
        float rm0 = -1e30f, rm1 = -1e30f;
#pragma unroll
        for (int j = 0; j < 8; j++) {
            rm0 = fmaxf(rm0, fmaxf(s[j][0], s[j][1]));
            rm1 = fmaxf(rm1, fmaxf(s[j][2], s[j][3]));
        }
        rm0 = fmaxf(rm0, __shfl_xor_sync(0xffffffffu, rm0, 1));
        rm0 = fmaxf(rm0, __shfl_xor_sync(0xffffffffu, rm0, 2));
        rm1 = fmaxf(rm1, __shfl_xor_sync(0xffffffffu, rm1, 1));
        rm1 = fmaxf(rm1, __shfl_xor_sync(0xffffffffu, rm1, 2));
        float mn0 = fmaxf(m0, rm0), mn1 = fmaxf(m1, rm1);
        float al0 = __expf(m0 - mn0), al1 = __expf(m1 - mn1);
        m0 = mn0; m1 = mn1;
        float rs0 = 0.f, rs1 = 0.f;
#pragma unroll
        for (int j = 0; j < 8; j++) {
            s[j][0] = __expf(s[j][0] - m0); rs0 += s[j][0];
            s[j][1] = __expf(s[j][1] - m0); rs0 += s[j][1];
            s[j][2] = __expf(s[j][2] - m1); rs1 += s[j][2];
            s[j][3] = __expf(s[j][3] - m1); rs1 += s[j][3];
        }
        rs0 += __shfl_xor_sync(0xffffffffu, rs0, 1);
        rs0 += __shfl_xor_sync(0xffffffffu, rs0, 2);
        rs1 += __shfl_xor_sync(0xffffffffu, rs1, 1);
        rs1 += __shfl_xor_sync(0xffffffffu, rs1, 2);
        l0 = l0 * al0 + rs0;
        l1 = l1 * al1 + rs1;
#pragma unroll
        for (int n = 0; n < 8; n++) {
            o[n][0] *= al0; o[n][1] *= al0; o[n][2] *= al1; o[n][3] *= al1;
        }

        // ---- O += P V  (P re-packed in regs: C-frag -> A-frag identity) ----
#pragma unroll
        for (int ka = 0; ka < 4; ka++) {
            const int j0 = 2 * ka, j1 = 2 * ka + 1;
            uint32_t ph[4], pl[4];
            {
                __nv_bfloat16 h00 = __float2bfloat16(s[j0][0]), h01 = __float2bfloat16(s[j0][1]);
                __nv_bfloat16 h02 = __float2bfloat16(s[j0][2]), h03 = __float2bfloat16(s[j0][3]);
                __nv_bfloat16 h10 = __float2bfloat16(s[j1][0]), h11 = __float2bfloat16(s[j1][1]);
                __nv_bfloat16 h12 = __float2bfloat16(s[j1][2]), h13 = __float2bfloat16(s[j1][3]);
                ph[0] = packbf(h00, h01); ph[1] = packbf(h02, h03);
                ph[2] = packbf(h10, h11); ph[3] = packbf(h12, h13);
                pl[0] = packbf(__float2bfloat16(s[j0][0] - __bfloat162float(h00)),
                               __float2bfloat16(s[j0][1] - __bfloat162float(h01)));
                pl[1] = packbf(__float2bfloat16(s[j0][2] - __bfloat162float(h02)),
                               __float2bfloat16(s[j0][3] - __bfloat162float(h03)));
                pl[2] = packbf(__float2bfloat16(s[j1][0] - __bfloat162float(h10)),
                               __float2bfloat16(s[j1][1] - __bfloat162float(h11)));
                pl[3] = packbf(__float2bfloat16(s[j1][2] - __bfloat162float(h12)),
                               __float2bfloat16(s[j1][3] - __bfloat162float(h13)));
            }
            const int ko = 16 * ka + 2 * tig;
#pragma unroll
            for (int n = 0; n < 8; n++) {
                int vr = 8 * n + g;
                uint32_t b0h = *(const uint32_t*)&Vh[vr * SSTR + ko];
                uint32_t b1h = *(const uint32_t*)&Vh[vr * SSTR + ko + 8];
                uint32_t b0l = *(const uint32_t*)&Vl[vr * SSTR + ko];
                uint32_t b1l = *(const uint32_t*)&Vl[vr * SSTR + ko + 8];
                mma16816(o[n], ph, b0h, b1h);
                mma16816(o[n], pl, b0h, b1h);
                mma16816(o[n], ph, b0l, b1l);
            }
        }
    }

    // ---- epilogue ----
    float inv0 = 1.f / l0, inv1 = 1.f / l1;
    int qr = q0 + 16 * w + g;
#pragma unroll
    for (int n = 0; n < 8; n++) {
        int col = cb + 8 * n + 2 * tig;
        *(float2*)&O[(size_t)(b * CN + qr) * CDIM + col]     = make_float2(o[n][0] * inv0, o[n][1] * inv0);
        *(float2*)&O[(size_t)(b * CN + qr + 8) * CDIM + col] = make_float2(o[n][2] * inv1, o[n][3] * inv1);
    }
}

// ---------------------------------------------------------------------------
extern "C" void kernel_launch(void* const* d_in, const int* in_sizes, int n_in,
                              void* d_out, int out_size)
{
    const float* x    = (const float*)d_in[0];
    const int*   mask = (const int*)  d_in[1];
    const float* W[4] = { (const float*)d_in[2], (const float*)d_in[3],
                          (const float*)d_in[4], (const float*)d_in[5] };
    float* out = (float*)d_out;

    float *qp, *kp, *vp, *op;
    __nv_bfloat16 *xh, *xl, *oh, *ol, *wh, *wl;
    cudaGetSymbolAddress((void**)&qp, g_q);
    cudaGetSymbolAddress((void**)&kp, g_k);
    cudaGetSymbolAddress((void**)&vp, g_v);
    cudaGetSymbolAddress((void**)&op, g_o);
    cudaGetSymbolAddress((void**)&xh, g_xhi);
    cudaGetSymbolAddress((void**)&xl, g_xlo);
    cudaGetSymbolAddress((void**)&oh, g_ohi);
    cudaGetSymbolAddress((void**)&ol, g_olo);
    cudaGetSymbolAddress((void**)&wh, g_wh);
    cudaGetSymbolAddress((void**)&wl, g_wl);

    const int M  = CB * CN;            // 8192
    const int NX = M * CDIM;
    const int NW = CDIM * CDIM;

    split_kernel<<<NX / 4 / 256, 256>>>(x, xh, xl, NX);
    for (int w = 0; w < 4; w++)
        split_kernel<<<NW / 4 / 256, 256>>>(W[w], wh + (size_t)w * NW, wl + (size_t)w * NW, NW);

    const int gsm = 4 * 128 * SSTR * (int)sizeof(__nv_bfloat16);              // 73728
    const int asm_b = (2 * 128 + 4 * 64) * SSTR * (int)sizeof(__nv_bfloat16)  // 73728
                    + 64 * (int)sizeof(int);
    cudaFuncSetAttribute(gemm_mma_kernel, cudaFuncAttributeMaxDynamicSharedMemorySize, gsm);
    cudaFuncSetAttribute(attn_mma_kernel, cudaFuncAttributeMaxDynamicSharedMemorySize, asm_b);

    dim3 ggrid(CDIM / 128, M / 128);   // (4, 64)
    gemm_mma_kernel<<<ggrid, 256, gsm>>>(xh, xl, wh + 0 * (size_t)NW, wl + 0 * (size_t)NW, qp, CDIM);
    gemm_mma_kernel<<<ggrid, 256, gsm>>>(xh, xl, wh + 1 * (size_t)NW, wl + 1 * (size_t)NW, kp, CDIM);
    gemm_mma_kernel<<<ggrid, 256, gsm>>>(xh, xl, wh + 2 * (size_t)NW, wl + 2 * (size_t)NW, vp, CDIM);

    attn_mma_kernel<<<dim3(CN / 128, CH * CB), 256, asm_b>>>(qp, kp, vp, mask, op);

    split_kernel<<<NX / 4 / 256, 256>>>(op, oh, ol, NX);
    gemm_mma_kernel<<<ggrid, 256, gsm>>>(oh, ol, wh + 3 * (size_t)NW, wl + 3 * (size_t)NW, out, CDIM);
}